// round 8
// baseline (speedup 1.0000x reference)
#include <cuda_runtime.h>
#include <cstdint>

#define BATCH   32
#define NPRED   22743
#define NCLS    80
#define KTOP    300
#define STRIDE  85
#define CAP     512
#define NBUCK   4096
#define NCTA1   45      // ceil(NPRED / 512) CTAs per batch in k1

// global scratch — zero at module load; every pass restores its own zeros
__device__ unsigned int       g_keys[BATCH * NPRED];
__device__ unsigned int       g_hist[BATCH * NBUCK];
__device__ unsigned int       g_cnt[BATCH];
__device__ unsigned long long g_cand[BATCH * CAP];
__device__ float2             g_ls[BATCH * KTOP];        // (label, score) per rank
__device__ unsigned long long g_supp[BATCH * KTOP * 5];
__device__ unsigned long long g_anyLow[BATCH * 5];
__device__ unsigned int       g_done1[BATCH];            // last-block counters
__device__ unsigned int       g_done3[BATCH];

__device__ __forceinline__ unsigned int bucket_of(unsigned int key) {
    // key in (0x3F000000, 0x3F800000]  (conf in (0.5, 1.0])
    return min((key - 0x3F000000u) >> 11, (unsigned)(NBUCK - 1));
}

// ---------------------------------------------------------------------------
// k1: key extraction + histogram (full chip). Last CTA per batch: threshold +
// compaction + scratch re-zero. Deadlock-free last-block pattern.
// ---------------------------------------------------------------------------
__global__ __launch_bounds__(512) void k1(const float* __restrict__ p) {
    const int b    = blockIdx.y;
    const int tid  = threadIdx.x;
    const int lane = tid & 31;
    const int wrp  = tid >> 5;

    // ---- extract keys for this CTA's slice ----
    {
        int n = blockIdx.x * 512 + tid;
        if (n < NPRED) {
            float x = __ldg(p + ((size_t)b * NPRED + n) * STRIDE + 4);
            unsigned int key = 0;
            if (x > 0.0f) {
                float c = 1.0f / (1.0f + expf(-x));
                if (c > 0.5f) key = __float_as_uint(c);   // conf > THR_CONF
            }
            g_keys[b * NPRED + n] = key;
            if (key) atomicAdd(&g_hist[b * NBUCK + bucket_of(key)], 1u);
        }
    }

    // ---- last-block election ----
    __shared__ int isLast;
    __threadfence();
    __syncthreads();
    if (tid == 0) isLast = (atomicAdd(&g_done1[b], 1u) == NCTA1 - 1);
    __syncthreads();
    if (!isLast) return;
    __threadfence();   // acquire: all batch-b writes now visible via L2

    // ---- threshold: suffix scan over 4096 buckets, 512 threads x 8 ----
    __shared__ unsigned int wsum[16], wsuf[17];
    __shared__ unsigned int sTotal;
    __shared__ int sT, scnt;
    if (tid == 0) { scnt = 0; sTotal = 0; }

    const unsigned int* h = g_hist + b * NBUCK;
    unsigned int v[8], s8 = 0;
#pragma unroll
    for (int i = 0; i < 8; i++) { v[i] = __ldg(h + tid * 8 + i); s8 += v[i]; }

    unsigned int suf = s8;
#pragma unroll
    for (int o = 1; o < 32; o <<= 1) {
        unsigned int t = __shfl_down_sync(0xffffffffu, suf, o);
        if (lane + o < 32) suf += t;
    }
    if (lane == 0) wsum[wrp] = suf;
    __syncthreads();
    if (wrp == 0) {
        unsigned int ws = (lane < 16) ? wsum[lane] : 0u;
#pragma unroll
        for (int o = 1; o < 32; o <<= 1) {
            unsigned int t = __shfl_down_sync(0xffffffffu, ws, o);
            if (lane + o < 32) ws += t;
        }
        if (lane < 16) wsuf[lane] = ws;
        if (lane == 0) { wsuf[16] = 0; sTotal = ws; }
    }
    __syncthreads();
    {
        unsigned int total = sTotal;
        unsigned int Kcap  = min((unsigned)KTOP, total);
        unsigned int inc   = suf + wsuf[wrp + 1];
        unsigned int above = inc - s8;
        if (Kcap > 0 && inc >= Kcap && above < Kcap) {
            unsigned int run = above;
            int T = tid * 8;
#pragma unroll
            for (int i = 7; i >= 0; i--) {
                run += v[i];
                if (run >= Kcap) { T = tid * 8 + i; break; }
            }
            sT = T;
        }
        if (Kcap == 0 && tid == 0) sT = NBUCK;
    }
    __syncthreads();
    const int T = sT;

    // ---- compaction (~303 survivors) ----
    const unsigned int* kb = g_keys + (size_t)b * NPRED;
#pragma unroll 1
    for (int k = 0; k < NCTA1; k++) {
        int n = tid + k * 512;
        if (n < NPRED) {
            unsigned int key = __ldg(kb + n);
            if (key && (int)bucket_of(key) >= T) {
                int pos = atomicAdd(&scnt, 1);
                if (pos < CAP)
                    g_cand[b * CAP + pos] = ((unsigned long long)key << 32) |
                                            (0xFFFFFFFFu - (unsigned)n);
            }
        }
    }
    __syncthreads();
    int cc = min(scnt, CAP);
    for (int i = tid; i < CAP; i += 512)
        if (i >= cc) g_cand[b * CAP + i] = 0ull;   // zero-fill tail
    if (tid == 0) g_cnt[b] = (unsigned)cc;

    // ---- restore zeros for next pass ----
    for (int i = tid; i < NBUCK; i += 512) g_hist[b * NBUCK + i] = 0u;
    if (tid == 0) g_done1[b] = 0u;
}

// ---------------------------------------------------------------------------
// k2: full-chip rank + decode + argmax. One 8-lane group per candidate slot.
// ---------------------------------------------------------------------------
__global__ __launch_bounds__(256) void k2(const float* __restrict__ p,
                                          const float* __restrict__ ancs,
                                          const float* __restrict__ fsz,
                                          float* __restrict__ outBoxes) {
    const int chunk = blockIdx.x;       // 0..15
    const int b     = blockIdx.y;
    const int tid   = threadIdx.x;
    const int sub   = tid & 7;
    const int grp   = tid >> 3;
    const int slot  = chunk * 32 + grp;

    __shared__ unsigned long long sc[CAP];
    sc[tid]       = g_cand[b * CAP + tid];
    sc[tid + 256] = g_cand[b * CAP + tid + 256];
    __syncthreads();

    unsigned long long my = sc[slot];

    int r = 0;
#pragma unroll 8
    for (int j = sub; j < CAP; j += 8) r += (sc[j] > my);
    r += __shfl_down_sync(0xffffffffu, r, 4, 8);
    r += __shfl_down_sync(0xffffffffu, r, 2, 8);
    r += __shfl_down_sync(0xffffffffu, r, 1, 8);
    r  = __shfl_sync(0xffffffffu, r, 0, 8);

    if (my != 0ull && r < KTOP) {
        int n = (int)(0xFFFFFFFFu - (unsigned int)(my & 0xFFFFFFFFull));
        const float* pr = p + ((size_t)b * NPRED + n) * STRIDE;

        unsigned long long best = 0ull;
#pragma unroll
        for (int k = 0; k < 10; k++) {
            int c = sub + k * 8;
            unsigned int ub = __float_as_uint(__ldg(pr + 5 + c));
            ub = (ub & 0x80000000u) ? ~ub : (ub | 0x80000000u);   // order-preserving
            unsigned long long key = ((unsigned long long)ub << 8) | (unsigned)(255 - c);
            if (key > best) best = key;
        }
        {
            unsigned long long t;
            t = __shfl_down_sync(0xffffffffu, best, 4, 8); if (t > best) best = t;
            t = __shfl_down_sync(0xffffffffu, best, 2, 8); if (t > best) best = t;
            t = __shfl_down_sync(0xffffffffu, best, 1, 8); if (t > best) best = t;
        }
        if (sub == 0) {
            int label = 256 - (int)(best & 0xFFull);   // argmax + 1, tie -> lowest
            float tx = __ldg(pr + 0), ty = __ldg(pr + 1);
            float tw = __ldg(pr + 2), th = __ldg(pr + 3);
            float fs = __ldg(fsz + (size_t)n * 2);
            float4 an = *reinterpret_cast<const float4*>(ancs + (size_t)n * 4);
            float cx = 1.0f / (1.0f + expf(-tx)) / fs + an.x;
            float cy = 1.0f / (1.0f + expf(-ty)) / fs + an.y;
            float w  = expf(tw) * an.z;
            float hh = expf(th) * an.w;
            *reinterpret_cast<float4*>(outBoxes + (size_t)(b * KTOP + r) * 4) =
                make_float4(cx - 0.5f * w, cy - 0.5f * hh, cx + 0.5f * w, cy + 0.5f * hh);
            g_ls[b * KTOP + r] =
                make_float2((float)label, __uint_as_float((unsigned int)(my >> 32)));
        }
    }
}

// ---------------------------------------------------------------------------
// k3: suppression bitmask (grid (5,32)); last CTA per batch runs the greedy
// scan + final writes + scratch resets. Pad-slot garbage is harmless: pad
// ranks are never valid, so their keep bits stay 0 in kw.
// ---------------------------------------------------------------------------
__global__ __launch_bounds__(320) void k3(float* __restrict__ outBoxes,
                                          float* __restrict__ outIds,
                                          float* __restrict__ outLabels,
                                          float* __restrict__ outScores) {
    const int w   = blockIdx.x;     // 0..4
    const int b   = blockIdx.y;
    const int tid = threadIdx.x;

    __shared__ float sl[KTOP], st[KTOP], sr[KTOP], sb[KTOP], sa[KTOP];
    if (tid < KTOP) {
        float4 bx = *reinterpret_cast<const float4*>(outBoxes + (size_t)(b * KTOP + tid) * 4);
        float off = 4.0f * g_ls[b * KTOP + tid].x;
        float l = bx.x + off, t0 = bx.y + off, r = bx.z + off, bt = bx.w + off;
        sl[tid] = l; st[tid] = t0; sr[tid] = r; sb[tid] = bt;
        sa[tid] = fmaxf(r - l, 0.0f) * fmaxf(bt - t0, 0.0f);
    }
    __syncthreads();

    if (tid < KTOP) {
        const int i = tid;
        float li = sl[i], ti = st[i], ri = sr[i], bi = sb[i], ai = sa[i];
        unsigned long long bits = 0ull;
        int j0 = w * 64;
        int jend = min(j0 + 64, KTOP);
        for (int j = j0; j < jend; j++) {
            float ltx = fmaxf(li, sl[j]);
            float lty = fmaxf(ti, st[j]);
            float rbx = fminf(ri, sr[j]);
            float rby = fminf(bi, sb[j]);
            float iw = fmaxf(rbx - ltx, 0.0f);
            float ih = fmaxf(rby - lty, 0.0f);
            float inter = iw * ih;
            float iou = inter / (ai + sa[j] - inter + 1e-7f);
            if (iou > 0.3f) bits |= 1ull << (j - j0);
        }
        g_supp[(b * KTOP + i) * 5 + w] = bits;

        unsigned long long low = 0ull;     // suppressors with j < i
        int iw6 = i >> 6;
        if (w < iw6)       low = bits;
        else if (w == iw6) low = bits & ((1ull << (i & 63)) - 1ull);
        if (low) atomicOr(&g_anyLow[b * 5 + iw6], 1ull << (i & 63));
    }

    // ---- last-block election ----
    __shared__ int isLast;
    __threadfence();
    __syncthreads();
    if (tid == 0) isLast = (atomicAdd(&g_done3[b], 1u) == 4);
    __syncthreads();
    if (!isLast) return;
    __threadfence();   // acquire

    // ---- scan phase (one CTA per batch) ----
    __shared__ unsigned long long ssup[KTOP * 5];   // 12 KB
    __shared__ float ssc[KTOP];
    __shared__ int   slab[KTOP];
    __shared__ unsigned long long validw[5], keepw[5];

    if (tid < 5) validw[tid] = 0ull;
    for (int t = tid; t < KTOP * 5; t += 320)
        ssup[t] = g_supp[b * (KTOP * 5) + t];

    int cc = min((int)g_cnt[b], KTOP);
    if (tid < KTOP) {
        if (tid < cc) {
            float2 ls = g_ls[b * KTOP + tid];
            ssc[tid]  = ls.y;
            slab[tid] = (int)ls.x;
        } else {   // pathological pad (never with this data)
            ssc[tid] = 0.0f; slab[tid] = 0;
            *reinterpret_cast<float4*>(outBoxes + (size_t)(b * KTOP + tid) * 4) =
                make_float4(0.f, 0.f, 0.f, 0.f);
        }
    }
    __syncthreads();
    if (tid < KTOP && ssc[tid] > 0.5f)
        atomicOr(&validw[tid >> 6], 1ull << (tid & 63));
    __syncthreads();

    if (tid == 0) {
        unsigned long long kw[5] = {0ull, 0ull, 0ull, 0ull, 0ull};
#pragma unroll
        for (int ww = 0; ww < 5; ww++) {
            unsigned long long cur = 0ull;
            unsigned long long alw = g_anyLow[b * 5 + ww];
            unsigned long long vmw = validw[ww];
            int jend = (ww < 4) ? 64 : (KTOP - 256);
            for (int jj = 0; jj < jend; jj++) {
                unsigned long long bit = 1ull << jj;
                if (vmw & bit) {
                    if (!(alw & bit)) {
                        cur |= bit;       // no lower-ranked overlap at all
                    } else {
                        int i = ww * 64 + jj;
                        unsigned long long s = (ssup[i * 5 + 0] & kw[0]) |
                                               (ssup[i * 5 + 1] & kw[1]) |
                                               (ssup[i * 5 + 2] & kw[2]) |
                                               (ssup[i * 5 + 3] & kw[3]) |
                                               (ssup[i * 5 + 4] & kw[4]) |
                                               (ssup[i * 5 + ww] & cur);
                        if (s == 0ull) cur |= bit;
                    }
                }
            }
            kw[ww] = cur;
        }
#pragma unroll
        for (int ww = 0; ww < 5; ww++) keepw[ww] = kw[ww];
    }
    __syncthreads();

    if (tid < KTOP) {
        bool kp = (keepw[tid >> 6] >> (tid & 63)) & 1ull;
        outIds[b * KTOP + tid]    = (float)b;
        outScores[b * KTOP + tid] = kp ? ssc[tid] : 0.0f;
        outLabels[b * KTOP + tid] = kp ? (float)slab[tid] : 0.0f;
    }

    // ---- restore zeros for next pass ----
    if (tid < 5)  g_anyLow[b * 5 + tid] = 0ull;
    if (tid == 0) g_done3[b] = 0u;
}

// ---------------------------------------------------------------------------
extern "C" void kernel_launch(void* const* d_in, const int* in_sizes, int n_in,
                              void* d_out, int out_size) {
    const float* p    = (const float*)d_in[0];
    const float* ancs = (const float*)d_in[1];
    const float* fsz  = (const float*)d_in[2];
    float* out = (float*)d_out;

    float* outIds    = out;
    float* outBoxes  = out + BATCH * KTOP;
    float* outLabels = out + BATCH * KTOP * 5;
    float* outScores = out + BATCH * KTOP * 6;

    dim3 grid1(NCTA1, BATCH);      // 45 x 32
    k1<<<grid1, 512>>>(p);
    dim3 grid2(CAP / 32, BATCH);   // 16 x 32
    k2<<<grid2, 256>>>(p, ancs, fsz, outBoxes);
    dim3 grid3(5, BATCH);          // 5 x 32
    k3<<<grid3, 320>>>(outBoxes, outIds, outLabels, outScores);
}

// round 9
// speedup vs baseline: 1.0894x; 1.0894x over previous
#include <cuda_runtime.h>
#include <cstdint>

#define BATCH   32
#define NPRED   22743
#define NCLS    80
#define KTOP    300
#define STRIDE  85
#define CAP     512
#define NBUCK   4096
#define RPC     2048    // rows per CTA in k1 (512 threads x 4)
#define NCTA1   12      // ceil(NPRED / RPC)

// global scratch — zero at module load; every pass restores its own zeros
__device__ unsigned int       g_keys[BATCH * NPRED];
__device__ unsigned int       g_hist[BATCH * NBUCK];
__device__ unsigned int       g_cnt[BATCH];
__device__ unsigned long long g_cand[BATCH * CAP];
__device__ float2             g_ls[BATCH * KTOP];        // (label, score) per rank
__device__ unsigned long long g_supp[BATCH * KTOP * 5];
__device__ unsigned long long g_anyLow[BATCH * 5];
__device__ unsigned int       g_done1[BATCH];            // last-block counters
__device__ unsigned int       g_done3[BATCH];

__device__ __forceinline__ unsigned int bucket_of(unsigned int key) {
    // key in (0x3F000000, 0x3F800000]  (conf in (0.5, 1.0])
    return min((key - 0x3F000000u) >> 11, (unsigned)(NBUCK - 1));
}

// ---------------------------------------------------------------------------
// k1: conf scan with 4 outstanding loads per thread (DRAM-BW bound), then the
// last CTA per batch computes threshold + compaction + scratch re-zero.
// ---------------------------------------------------------------------------
__global__ __launch_bounds__(512) void k1(const float* __restrict__ p) {
    const int b    = blockIdx.y;
    const int tid  = threadIdx.x;
    const int lane = tid & 31;
    const int wrp  = tid >> 5;

    // ---- phase 1: 4 independent strided loads, issued before any use ----
    {
        const int n0 = blockIdx.x * RPC + tid;
        float x0 = -1.f, x1 = -1.f, x2 = -1.f, x3 = -1.f;
        const float* base = p + (size_t)b * NPRED * STRIDE + 4;
        if (n0              < NPRED) x0 = __ldg(base + (size_t)(n0           ) * STRIDE);
        if (n0 + 512        < NPRED) x1 = __ldg(base + (size_t)(n0 + 512     ) * STRIDE);
        if (n0 + 1024       < NPRED) x2 = __ldg(base + (size_t)(n0 + 1024    ) * STRIDE);
        if (n0 + 1536       < NPRED) x3 = __ldg(base + (size_t)(n0 + 1536    ) * STRIDE);

        float xs[4] = {x0, x1, x2, x3};
#pragma unroll
        for (int k = 0; k < 4; k++) {
            int n = n0 + k * 512;
            if (n < NPRED) {
                float x = xs[k];
                unsigned int key = 0;
                if (x > 0.0f) {
                    float c = 1.0f / (1.0f + expf(-x));
                    if (c > 0.5f) key = __float_as_uint(c);   // conf > THR_CONF
                }
                g_keys[b * NPRED + n] = key;
                if (key) atomicAdd(&g_hist[b * NBUCK + bucket_of(key)], 1u);
            }
        }
    }

    // ---- last-block election (deadlock-free: sole winner continues) ----
    __shared__ int isLast;
    __threadfence();
    __syncthreads();
    if (tid == 0) isLast = (atomicAdd(&g_done1[b], 1u) == NCTA1 - 1);
    __syncthreads();
    if (!isLast) return;
    __threadfence();   // acquire: all batch-b writes visible

    // ---- threshold: suffix scan over 4096 buckets ----
    __shared__ unsigned int wsum[16], wsuf[17];
    __shared__ unsigned int sTotal;
    __shared__ int sT, scnt;
    if (tid == 0) { scnt = 0; sTotal = 0; }

    const unsigned int* h = g_hist + b * NBUCK;
    unsigned int v[8], s8 = 0;
#pragma unroll
    for (int i = 0; i < 8; i++) { v[i] = __ldg(h + tid * 8 + i); s8 += v[i]; }

    unsigned int suf = s8;
#pragma unroll
    for (int o = 1; o < 32; o <<= 1) {
        unsigned int t = __shfl_down_sync(0xffffffffu, suf, o);
        if (lane + o < 32) suf += t;
    }
    if (lane == 0) wsum[wrp] = suf;
    __syncthreads();
    if (wrp == 0) {
        unsigned int ws = (lane < 16) ? wsum[lane] : 0u;
#pragma unroll
        for (int o = 1; o < 32; o <<= 1) {
            unsigned int t = __shfl_down_sync(0xffffffffu, ws, o);
            if (lane + o < 32) ws += t;
        }
        if (lane < 16) wsuf[lane] = ws;
        if (lane == 0) { wsuf[16] = 0; sTotal = ws; }
    }
    __syncthreads();
    {
        unsigned int total = sTotal;
        unsigned int Kcap  = min((unsigned)KTOP, total);
        unsigned int inc   = suf + wsuf[wrp + 1];
        unsigned int above = inc - s8;
        if (Kcap > 0 && inc >= Kcap && above < Kcap) {
            unsigned int run = above;
            int T = tid * 8;
#pragma unroll
            for (int i = 7; i >= 0; i--) {
                run += v[i];
                if (run >= Kcap) { T = tid * 8 + i; break; }
            }
            sT = T;
        }
        if (Kcap == 0 && tid == 0) sT = NBUCK;
    }
    __syncthreads();
    const int T = sT;

    // ---- compaction (~303 survivors), L2-hot keys, 4-way MLP ----
    const unsigned int* kb = g_keys + (size_t)b * NPRED;
    for (int k0 = 0; k0 < 48; k0 += 4) {           // 48*512 = 24576 >= NPRED
        unsigned int kv[4] = {0u, 0u, 0u, 0u};
#pragma unroll
        for (int j = 0; j < 4; j++) {
            int n = tid + (k0 + j) * 512;
            if (n < NPRED) kv[j] = __ldg(kb + n);
        }
#pragma unroll
        for (int j = 0; j < 4; j++) {
            unsigned int key = kv[j];
            if (key && (int)bucket_of(key) >= T) {
                int n = tid + (k0 + j) * 512;
                int pos = atomicAdd(&scnt, 1);
                if (pos < CAP)
                    g_cand[b * CAP + pos] = ((unsigned long long)key << 32) |
                                            (0xFFFFFFFFu - (unsigned)n);
            }
        }
    }
    __syncthreads();
    int cc = min(scnt, CAP);
    if (tid < CAP && tid >= cc) g_cand[b * CAP + tid] = 0ull;   // zero-fill tail
    if (tid == 0) g_cnt[b] = (unsigned)cc;

    // ---- restore zeros for next pass ----
    for (int i = tid; i < NBUCK; i += 512) g_hist[b * NBUCK + i] = 0u;
    if (tid == 0) g_done1[b] = 0u;
}

// ---------------------------------------------------------------------------
// k2: full-chip rank + decode + argmax. 512 threads = 64 groups of 8 lanes.
// ---------------------------------------------------------------------------
__global__ __launch_bounds__(512) void k2(const float* __restrict__ p,
                                          const float* __restrict__ ancs,
                                          const float* __restrict__ fsz,
                                          float* __restrict__ outBoxes) {
    const int chunk = blockIdx.x;       // 0..7
    const int b     = blockIdx.y;
    const int tid   = threadIdx.x;
    const int sub   = tid & 7;
    const int grp   = tid >> 3;         // 0..63
    const int slot  = chunk * 64 + grp; // 0..511

    __shared__ unsigned long long sc[CAP];
    sc[tid] = g_cand[b * CAP + tid];
    __syncthreads();

    unsigned long long my = sc[slot];

    int r = 0;
#pragma unroll 8
    for (int j = sub; j < CAP; j += 8) r += (sc[j] > my);
    r += __shfl_down_sync(0xffffffffu, r, 4, 8);
    r += __shfl_down_sync(0xffffffffu, r, 2, 8);
    r += __shfl_down_sync(0xffffffffu, r, 1, 8);
    r  = __shfl_sync(0xffffffffu, r, 0, 8);

    if (my != 0ull && r < KTOP) {
        int n = (int)(0xFFFFFFFFu - (unsigned int)(my & 0xFFFFFFFFull));
        const float* pr = p + ((size_t)b * NPRED + n) * STRIDE;

        unsigned long long best = 0ull;
#pragma unroll
        for (int k = 0; k < 10; k++) {
            int c = sub + k * 8;
            unsigned int ub = __float_as_uint(__ldg(pr + 5 + c));
            ub = (ub & 0x80000000u) ? ~ub : (ub | 0x80000000u);   // order-preserving
            unsigned long long key = ((unsigned long long)ub << 8) | (unsigned)(255 - c);
            if (key > best) best = key;
        }
        {
            unsigned long long t;
            t = __shfl_down_sync(0xffffffffu, best, 4, 8); if (t > best) best = t;
            t = __shfl_down_sync(0xffffffffu, best, 2, 8); if (t > best) best = t;
            t = __shfl_down_sync(0xffffffffu, best, 1, 8); if (t > best) best = t;
        }
        if (sub == 0) {
            int label = 256 - (int)(best & 0xFFull);   // argmax + 1, tie -> lowest
            float tx = __ldg(pr + 0), ty = __ldg(pr + 1);
            float tw = __ldg(pr + 2), th = __ldg(pr + 3);
            float fs = __ldg(fsz + (size_t)n * 2);
            float4 an = *reinterpret_cast<const float4*>(ancs + (size_t)n * 4);
            float cx = 1.0f / (1.0f + expf(-tx)) / fs + an.x;
            float cy = 1.0f / (1.0f + expf(-ty)) / fs + an.y;
            float w  = expf(tw) * an.z;
            float hh = expf(th) * an.w;
            *reinterpret_cast<float4*>(outBoxes + (size_t)(b * KTOP + r) * 4) =
                make_float4(cx - 0.5f * w, cy - 0.5f * hh, cx + 0.5f * w, cy + 0.5f * hh);
            g_ls[b * KTOP + r] =
                make_float2((float)label, __uint_as_float((unsigned int)(my >> 32)));
        }
    }
}

// ---------------------------------------------------------------------------
// k3: suppression bitmask (grid (5,32)); last CTA per batch runs the greedy
// scan + final writes + scratch resets.
// ---------------------------------------------------------------------------
__global__ __launch_bounds__(320) void k3(float* __restrict__ outBoxes,
                                          float* __restrict__ outIds,
                                          float* __restrict__ outLabels,
                                          float* __restrict__ outScores) {
    const int w   = blockIdx.x;     // 0..4
    const int b   = blockIdx.y;
    const int tid = threadIdx.x;

    __shared__ float sl[KTOP], st[KTOP], sr[KTOP], sb[KTOP], sa[KTOP];
    if (tid < KTOP) {
        float4 bx = *reinterpret_cast<const float4*>(outBoxes + (size_t)(b * KTOP + tid) * 4);
        float off = 4.0f * g_ls[b * KTOP + tid].x;
        float l = bx.x + off, t0 = bx.y + off, r = bx.z + off, bt = bx.w + off;
        sl[tid] = l; st[tid] = t0; sr[tid] = r; sb[tid] = bt;
        sa[tid] = fmaxf(r - l, 0.0f) * fmaxf(bt - t0, 0.0f);
    }
    __syncthreads();

    if (tid < KTOP) {
        const int i = tid;
        float li = sl[i], ti = st[i], ri = sr[i], bi = sb[i], ai = sa[i];
        unsigned long long bits = 0ull;
        int j0 = w * 64;
        int jend = min(j0 + 64, KTOP);
        for (int j = j0; j < jend; j++) {
            float ltx = fmaxf(li, sl[j]);
            float lty = fmaxf(ti, st[j]);
            float rbx = fminf(ri, sr[j]);
            float rby = fminf(bi, sb[j]);
            float iw = fmaxf(rbx - ltx, 0.0f);
            float ih = fmaxf(rby - lty, 0.0f);
            float inter = iw * ih;
            float iou = inter / (ai + sa[j] - inter + 1e-7f);
            if (iou > 0.3f) bits |= 1ull << (j - j0);
        }
        g_supp[(b * KTOP + i) * 5 + w] = bits;

        unsigned long long low = 0ull;     // suppressors with j < i
        int iw6 = i >> 6;
        if (w < iw6)       low = bits;
        else if (w == iw6) low = bits & ((1ull << (i & 63)) - 1ull);
        if (low) atomicOr(&g_anyLow[b * 5 + iw6], 1ull << (i & 63));
    }

    // ---- last-block election ----
    __shared__ int isLast;
    __threadfence();
    __syncthreads();
    if (tid == 0) isLast = (atomicAdd(&g_done3[b], 1u) == 4);
    __syncthreads();
    if (!isLast) return;
    __threadfence();   // acquire

    // ---- greedy scan (one CTA per batch) ----
    __shared__ unsigned long long ssup[KTOP * 5];   // 12 KB
    __shared__ float ssc[KTOP];
    __shared__ int   slab[KTOP];
    __shared__ unsigned long long validw[5], keepw[5];

    if (tid < 5) validw[tid] = 0ull;
    for (int t = tid; t < KTOP * 5; t += 320)
        ssup[t] = g_supp[b * (KTOP * 5) + t];

    int cc = min((int)g_cnt[b], KTOP);
    if (tid < KTOP) {
        if (tid < cc) {
            float2 ls = g_ls[b * KTOP + tid];
            ssc[tid]  = ls.y;
            slab[tid] = (int)ls.x;
        } else {   // pathological pad (never with this data)
            ssc[tid] = 0.0f; slab[tid] = 0;
            *reinterpret_cast<float4*>(outBoxes + (size_t)(b * KTOP + tid) * 4) =
                make_float4(0.f, 0.f, 0.f, 0.f);
        }
    }
    __syncthreads();
    if (tid < KTOP && ssc[tid] > 0.5f)
        atomicOr(&validw[tid >> 6], 1ull << (tid & 63));
    __syncthreads();

    if (tid == 0) {
        unsigned long long kw[5] = {0ull, 0ull, 0ull, 0ull, 0ull};
#pragma unroll
        for (int ww = 0; ww < 5; ww++) {
            unsigned long long cur = 0ull;
            unsigned long long alw = g_anyLow[b * 5 + ww];
            unsigned long long vmw = validw[ww];
            int jend = (ww < 4) ? 64 : (KTOP - 256);
            for (int jj = 0; jj < jend; jj++) {
                unsigned long long bit = 1ull << jj;
                if (vmw & bit) {
                    if (!(alw & bit)) {
                        cur |= bit;       // no lower-ranked overlap at all
                    } else {
                        int i = ww * 64 + jj;
                        unsigned long long s = (ssup[i * 5 + 0] & kw[0]) |
                                               (ssup[i * 5 + 1] & kw[1]) |
                                               (ssup[i * 5 + 2] & kw[2]) |
                                               (ssup[i * 5 + 3] & kw[3]) |
                                               (ssup[i * 5 + 4] & kw[4]) |
                                               (ssup[i * 5 + ww] & cur);
                        if (s == 0ull) cur |= bit;
                    }
                }
            }
            kw[ww] = cur;
        }
#pragma unroll
        for (int ww = 0; ww < 5; ww++) keepw[ww] = kw[ww];
    }
    __syncthreads();

    if (tid < KTOP) {
        bool kp = (keepw[tid >> 6] >> (tid & 63)) & 1ull;
        outIds[b * KTOP + tid]    = (float)b;
        outScores[b * KTOP + tid] = kp ? ssc[tid] : 0.0f;
        outLabels[b * KTOP + tid] = kp ? (float)slab[tid] : 0.0f;
    }

    // ---- restore zeros for next pass ----
    if (tid < 5)  g_anyLow[b * 5 + tid] = 0ull;
    if (tid == 0) g_done3[b] = 0u;
}

// ---------------------------------------------------------------------------
extern "C" void kernel_launch(void* const* d_in, const int* in_sizes, int n_in,
                              void* d_out, int out_size) {
    const float* p    = (const float*)d_in[0];
    const float* ancs = (const float*)d_in[1];
    const float* fsz  = (const float*)d_in[2];
    float* out = (float*)d_out;

    float* outIds    = out;
    float* outBoxes  = out + BATCH * KTOP;
    float* outLabels = out + BATCH * KTOP * 5;
    float* outScores = out + BATCH * KTOP * 6;

    dim3 grid1(NCTA1, BATCH);      // 12 x 32
    k1<<<grid1, 512>>>(p);
    dim3 grid2(CAP / 64, BATCH);   // 8 x 32
    k2<<<grid2, 512>>>(p, ancs, fsz, outBoxes);
    dim3 grid3(5, BATCH);          // 5 x 32
    k3<<<grid3, 320>>>(outBoxes, outIds, outLabels, outScores);
}